// round 6
// baseline (speedup 1.0000x reference)
#include <cuda_runtime.h>
#include <cuda_bf16.h>
#include <cstdint>

// Problem constants
#define BSZ   512
#define NNODE 22
#define INDIM 128
#define HID   256
#define MROWS (BSZ * NNODE)   // 11264

// Scratch (device globals: no allocation allowed)
__device__ float g_hs[BSZ * HID];   // segment sum over 22 nodes
__device__ float g_S [BSZ * HID];   // layer-0 output
__device__ float g_t [BSZ * HID];   // layer-1 output

// ---------------------------------------------------------------------------
// tf32 helpers (3xTF32 split -> fp32-grade accuracy)
// ---------------------------------------------------------------------------
__device__ __forceinline__ void f32_to_tf32x2(float v, uint32_t& hi, uint32_t& lo) {
    asm("cvt.rna.tf32.f32 %0, %1;" : "=r"(hi) : "f"(v));
    float r = v - __uint_as_float(hi);
    asm("cvt.rna.tf32.f32 %0, %1;" : "=r"(lo) : "f"(r));
}

__device__ __forceinline__ void mma_tf32(float* d, const uint32_t* a,
                                         uint32_t b0, uint32_t b1) {
    asm volatile(
        "mma.sync.aligned.m16n8k8.row.col.f32.tf32.tf32.f32 "
        "{%0,%1,%2,%3}, {%4,%5,%6,%7}, {%8,%9}, {%0,%1,%2,%3};"
        : "+f"(d[0]), "+f"(d[1]), "+f"(d[2]), "+f"(d[3])
        : "r"(a[0]), "r"(a[1]), "r"(a[2]), "r"(a[3]), "r"(b0), "r"(b1));
}

// ---------------------------------------------------------------------------
// K1 (tensor): h = relu(x @ (We1[:128]+We1[128:]) + be1), fused 22-row reduce.
// Block: 88 rows (4 groups of 22, padded to 96 = 6 m16-tiles) x 64 cols.
// 256 threads = 8 warps; warp w owns n-tile w (8 cols), all 6 m-tiles.
// BK=32, 4 k-chunks. grid (4, 128) = 512 blocks.
// ---------------------------------------------------------------------------
__global__ __launch_bounds__(256)
void gemm1_mma(const float* __restrict__ x,
               const float* __restrict__ We1,
               const float* __restrict__ be1) {
    // union: stage phase {As[96][36], Bs[32][72]} = 23040 B; hbuf[96][72] = 27648 B
    __shared__ __align__(16) float smem[96 * 72];
    float* As = smem;               // [96][36]  (stride 36 -> frag loads conflict-free)
    float* Bs = smem + 96 * 36;     // [32][72]
    float* hb = smem;               // [96][72]  (aliases; used after final sync)

    const int t  = threadIdx.x;
    const int w  = t >> 5;
    const int l  = t & 31;
    const int g  = l >> 2;
    const int t4 = l & 3;
    const int n0 = blockIdx.x * 64;
    const int m0 = blockIdx.y * 88;

    float acc[6][4];
#pragma unroll
    for (int mt = 0; mt < 6; mt++)
#pragma unroll
        for (int j = 0; j < 4; j++) acc[mt][j] = 0.0f;

    for (int kc = 0; kc < 4; kc++) {
        const int k0 = kc * 32;
        // ---- stage A [96 x 32] (rows >= 88 zero-padded) ----
#pragma unroll
        for (int j = 0; j < 3; j++) {
            int idx = j * 256 + t;
            int row = idx >> 3;
            int kq  = (idx & 7) * 4;
            float4 v = make_float4(0.f, 0.f, 0.f, 0.f);
            if (row < 88)
                v = *(const float4*)&x[(size_t)(m0 + row) * INDIM + k0 + kq];
            *(float4*)&As[row * 36 + kq] = v;
        }
        // ---- stage B [32 x 64] with inline We1 fold ----
#pragma unroll
        for (int j = 0; j < 2; j++) {
            int idx = j * 256 + t;
            int k  = idx >> 4;
            int nq = (idx & 15) * 4;
            float4 a = *(const float4*)&We1[(size_t)(k0 + k) * HID + n0 + nq];
            float4 b = *(const float4*)&We1[(size_t)(k0 + k + INDIM) * HID + n0 + nq];
            a.x += b.x; a.y += b.y; a.z += b.z; a.w += b.w;
            *(float4*)&Bs[k * 72 + nq] = a;
        }
        __syncthreads();

        // ---- compute: 4 k-steps of 8 ----
#pragma unroll
        for (int ks = 0; ks < 4; ks++) {
            const int ki = ks * 8;
            uint32_t bh0, bl0, bh1, bl1;
            f32_to_tf32x2(Bs[(ki + t4) * 72 + 8 * w + g],     bh0, bl0);
            f32_to_tf32x2(Bs[(ki + t4 + 4) * 72 + 8 * w + g], bh1, bl1);
#pragma unroll
            for (int mt = 0; mt < 6; mt++) {
                const int rb = mt * 16;
                uint32_t ah[4], al[4];
                f32_to_tf32x2(As[(rb + g) * 36 + ki + t4],         ah[0], al[0]);
                f32_to_tf32x2(As[(rb + g + 8) * 36 + ki + t4],     ah[1], al[1]);
                f32_to_tf32x2(As[(rb + g) * 36 + ki + t4 + 4],     ah[2], al[2]);
                f32_to_tf32x2(As[(rb + g + 8) * 36 + ki + t4 + 4], ah[3], al[3]);
                mma_tf32(acc[mt], ah, bh0, bh1);   // hi*hi
                mma_tf32(acc[mt], ah, bl0, bl1);   // hi*lo
                mma_tf32(acc[mt], al, bh0, bh1);   // lo*hi
            }
        }
        __syncthreads();
    }

    // ---- epilogue: h = relu(acc + bias) -> smem (stride 72) ----
    const int   cc  = 8 * w + 2 * t4;
    const float bv0 = be1[n0 + cc];
    const float bv1 = be1[n0 + cc + 1];
#pragma unroll
    for (int mt = 0; mt < 6; mt++) {
        const int r0 = mt * 16 + g;
        const int r1 = r0 + 8;
        hb[r0 * 72 + cc]     = fmaxf(acc[mt][0] + bv0, 0.0f);
        hb[r0 * 72 + cc + 1] = fmaxf(acc[mt][1] + bv1, 0.0f);
        hb[r1 * 72 + cc]     = fmaxf(acc[mt][2] + bv0, 0.0f);
        hb[r1 * 72 + cc + 1] = fmaxf(acc[mt][3] + bv1, 0.0f);
    }
    __syncthreads();

    // ---- 22-row segment reduce: 4 groups x 64 cols, 1 output/thread ----
    {
        const int gg = t >> 6;     // 0..3
        const int c  = t & 63;
        float s = 0.0f;
#pragma unroll
        for (int i = 0; i < 22; i++)
            s += hb[(22 * gg + i) * 72 + c];
        g_hs[(size_t)(blockIdx.y * 4 + gg) * HID + n0 + c] = s;
    }
}

// ---------------------------------------------------------------------------
// Tensor-core tail: C[512,256] = act(A @ W + biasScale*bias) per layer.
// Block = 16x32 tile, 128 threads, warp split-K + smem reduce. Grid (8,32).
// ---------------------------------------------------------------------------
template <bool RELU, bool BCAST>
__global__ __launch_bounds__(128)
void tail_mma(const float* __restrict__ A,
              const float* __restrict__ W,
              const float* __restrict__ bias,
              float biasScale,
              float* __restrict__ C) {
    __shared__ float As[16][256];      // swizzled: col k stored at k ^ (4*(m&7))
    __shared__ float Bst[32 * 256];    // B^T swizzled; reused as reduce scratch

    float (*Bs)[256] = reinterpret_cast<float(*)[256]>(Bst);

    const int t  = threadIdx.x;
    const int w  = t >> 5;
    const int l  = t & 31;
    const int g  = l >> 2;
    const int t4 = l & 3;
    const int m0 = blockIdx.y * 16;
    const int n0 = blockIdx.x * 32;

    // ---- Stage A tile [16 x 256] (coalesced float4, XOR swizzle) ----
#pragma unroll
    for (int i = 0; i < 8; i++) {
        int flat = i * 512 + t * 4;
        int m = flat >> 8, k = flat & 255;
        float4 v = *(const float4*)&A[(size_t)(m0 + m) * 256 + k];
        *(float4*)&As[m][k ^ (4 * (m & 7))] = v;
    }
    // ---- Stage B^T [32 x 256] via float4 global loads + smem transpose ----
    {
        const int c8 = t & 7;        // n-quad
        const int kr = t >> 3;       // 0..15
        const int nb = 4 * c8;
#pragma unroll 4
        for (int j = 0; j < 16; j++) {
            int k = kr + 16 * j;
            float4 v = *(const float4*)&W[(size_t)k * 256 + n0 + nb];
            Bs[nb]    [k ^ (4 * ((nb)     & 7))] = v.x;
            Bs[nb + 1][k ^ (4 * ((nb + 1) & 7))] = v.y;
            Bs[nb + 2][k ^ (4 * ((nb + 2) & 7))] = v.z;
            Bs[nb + 3][k ^ (4 * ((nb + 3) & 7))] = v.w;
        }
    }
    __syncthreads();

    // ---- Compute: warp w covers k in [64w, 64w+64) ----
    float acc[4][4];
#pragma unroll
    for (int nt = 0; nt < 4; nt++)
#pragma unroll
        for (int j = 0; j < 4; j++) acc[nt][j] = 0.0f;

    const int sw = 4 * g;

#pragma unroll
    for (int c = 0; c < 8; c++) {
        const int k0  = w * 64 + c * 8;
        const int ka  = (k0 + t4) ^ sw;
        const int kb2 = (k0 + t4 + 4) ^ sw;

        uint32_t ah[4], al[4];
        f32_to_tf32x2(As[g][ka],      ah[0], al[0]);
        f32_to_tf32x2(As[g + 8][ka],  ah[1], al[1]);
        f32_to_tf32x2(As[g][kb2],     ah[2], al[2]);
        f32_to_tf32x2(As[g + 8][kb2], ah[3], al[3]);

#pragma unroll
        for (int nt = 0; nt < 4; nt++) {
            uint32_t bh0, bl0, bh1, bl1;
            f32_to_tf32x2(Bs[nt * 8 + g][ka],  bh0, bl0);
            f32_to_tf32x2(Bs[nt * 8 + g][kb2], bh1, bl1);
            mma_tf32(acc[nt], ah, bh0, bh1);
            mma_tf32(acc[nt], ah, bl0, bl1);
            mma_tf32(acc[nt], al, bh0, bh1);
        }
    }
    __syncthreads();   // all warps done reading Bs -> reuse as scratch

    // ---- Cross-warp split-K reduce via smem ----
    typedef float RedT[16][33];
    RedT* red = reinterpret_cast<RedT*>(Bst);
#pragma unroll
    for (int nt = 0; nt < 4; nt++) {
        const int col = nt * 8 + 2 * t4;
        red[w][g][col]         = acc[nt][0];
        red[w][g][col + 1]     = acc[nt][1];
        red[w][g + 8][col]     = acc[nt][2];
        red[w][g + 8][col + 1] = acc[nt][3];
    }
    __syncthreads();

    // ---- Epilogue ----
    const int row = t >> 3;
    const int cb  = (t & 7) * 4;
    float v[4];
#pragma unroll
    for (int j = 0; j < 4; j++)
        v[j] = red[0][row][cb + j] + red[1][row][cb + j]
             + red[2][row][cb + j] + red[3][row][cb + j];

    const float4 bv = *(const float4*)&bias[n0 + cb];
    float4 o;
    o.x = v[0] + biasScale * bv.x;
    o.y = v[1] + biasScale * bv.y;
    o.z = v[2] + biasScale * bv.z;
    o.w = v[3] + biasScale * bv.w;
    if (RELU) {
        o.x = fmaxf(o.x, 0.0f); o.y = fmaxf(o.y, 0.0f);
        o.z = fmaxf(o.z, 0.0f); o.w = fmaxf(o.w, 0.0f);
    }

    const int rowg = m0 + row;
    const int colg = n0 + cb;
    if (!BCAST) {
        *(float4*)&C[(size_t)rowg * 256 + colg] = o;
    } else {
        size_t base = ((size_t)rowg * NNODE) * 256 + colg;
#pragma unroll
        for (int p = 0; p < NNODE; p++)
            *(float4*)&C[base + (size_t)p * 256] = o;
    }
}

// ---------------------------------------------------------------------------
extern "C" void kernel_launch(void* const* d_in, const int* in_sizes, int n_in,
                              void* d_out, int out_size) {
    const float* x   = (const float*)d_in[0];
    const float* We1 = (const float*)d_in[1];
    const float* be1 = (const float*)d_in[2];
    const float* We2 = (const float*)d_in[3];
    const float* be2 = (const float*)d_in[4];
    const float* Wn1 = (const float*)d_in[5];
    const float* bn1 = (const float*)d_in[6];
    const float* Wn2 = (const float*)d_in[7];
    const float* bn2 = (const float*)d_in[8];
    float* out = (float*)d_out;

    float *phs, *pS, *pt;
    cudaGetSymbolAddress((void**)&phs, g_hs);
    cudaGetSymbolAddress((void**)&pS,  g_S);
    cudaGetSymbolAddress((void**)&pt,  g_t);

    // K1 (tensor): fused GEMM1 (+We1 fold) + segment reduce -> g_hs [512 x 256]
    {
        dim3 grid(HID / 64, MROWS / 88);   // (4, 128) = 512 blocks
        gemm1_mma<<<grid, 256>>>(x, We1, be1);
    }

    dim3 tg(HID / 32, BSZ / 16);           // (8, 32) = 256 blocks

    // L0: S = hs @ We2 + 22*be2
    tail_mma<false, false><<<tg, 128>>>(phs, We2, be2, (float)NNODE, pS);
    // L1: t = relu(S @ Wn1 + bn1)
    tail_mma<true,  false><<<tg, 128>>>(pS,  Wn1, bn1, 1.0f, pt);
    // L2: out = t @ Wn2 + bn2, broadcast over 22 nodes
    tail_mma<false, true ><<<tg, 128>>>(pt,  Wn2, bn2, 1.0f, out);
}

// round 7
// speedup vs baseline: 1.5695x; 1.5695x over previous
#include <cuda_runtime.h>
#include <cuda_bf16.h>
#include <cstdint>

#define BSZ   512
#define NNODE 22
#define INDIM 128
#define HID   256
#define MROWS (BSZ * NNODE)   // 11264

// Scratch (device globals)
__device__ float g_hs[BSZ * HID];        // segment sum over 22 nodes
__device__ float g_S [BSZ * HID];        // layer-0 output
__device__ float g_t [BSZ * HID];        // layer-1 output
__device__ float g_Wt[3 * HID * HID];    // transposed tail weights: Wt[n][k]

// ---------------------------------------------------------------------------
// bf16 split-2 helpers: v = hi + lo, hi=bf16(v), lo=bf16(v-hi). Error ~2^-17.
// D += Ah*Bh + Ah*Bl + Al*Bh via mma.m16n8k16.bf16 (fp32 accum).
// ---------------------------------------------------------------------------
__device__ __forceinline__ void bf16_split2(float v0, float v1,
                                            uint32_t& hi, uint32_t& lo) {
    __nv_bfloat162 h = __float22bfloat162_rn(make_float2(v0, v1));
    float2 hf = __bfloat1622float2(h);
    __nv_bfloat162 l = __float22bfloat162_rn(make_float2(v0 - hf.x, v1 - hf.y));
    hi = *reinterpret_cast<uint32_t*>(&h);
    lo = *reinterpret_cast<uint32_t*>(&l);
}

__device__ __forceinline__ void mma_bf16(float* d, const uint32_t* a,
                                         uint32_t b0, uint32_t b1) {
    asm volatile(
        "mma.sync.aligned.m16n8k16.row.col.f32.bf16.bf16.f32 "
        "{%0,%1,%2,%3}, {%4,%5,%6,%7}, {%8,%9}, {%0,%1,%2,%3};"
        : "+f"(d[0]), "+f"(d[1]), "+f"(d[2]), "+f"(d[3])
        : "r"(a[0]), "r"(a[1]), "r"(a[2]), "r"(a[3]), "r"(b0), "r"(b1));
}

__device__ __forceinline__ uint32_t lds_u32(const __nv_bfloat16* p) {
    return *reinterpret_cast<const uint32_t*>(p);
}

// ---------------------------------------------------------------------------
// K1: h = relu(x @ (We1[:128]+We1[128:]) + be1), fused 22-row segment reduce.
// BM=176 (= 8 groups of 22 = 11 m16 tiles, exact), BN=64, BK=32.
// 256 threads / 8 warps; warp w owns n8-tile w, all 11 m-tiles.
// grid (4, 64+3): blockIdx.y >= 64 -> transpose role for tail weights.
// ---------------------------------------------------------------------------
__global__ __launch_bounds__(256)
void k1_mma(const float* __restrict__ x,
            const float* __restrict__ We1,
            const float* __restrict__ be1,
            const float* __restrict__ We2,
            const float* __restrict__ Wn1,
            const float* __restrict__ Wn2) {
    // ---- transpose role: 12 blocks, runs concurrent with main blocks ----
    if (blockIdx.y >= 64) {
        const int mat = blockIdx.y - 64;                 // 0..2
        const float* Wsrc = (mat == 0) ? We2 : (mat == 1) ? Wn1 : Wn2;
        float* dst = g_Wt + mat * HID * HID;
        const int k0 = blockIdx.x * 64;
        const int n  = threadIdx.x;                      // 0..255
        for (int kq = 0; kq < 64; kq += 4) {
            float4 v;
            v.x = Wsrc[(size_t)(k0 + kq + 0) * HID + n];
            v.y = Wsrc[(size_t)(k0 + kq + 1) * HID + n];
            v.z = Wsrc[(size_t)(k0 + kq + 2) * HID + n];
            v.w = Wsrc[(size_t)(k0 + kq + 3) * HID + n];
            *(float4*)&dst[(size_t)n * HID + k0 + kq] = v;
        }
        return;
    }

    // ---- smem: staging arrays (38400 B) union hbuf[176][68] f32 (47872 B) ----
    __shared__ __align__(16) unsigned char sm[176 * 68 * 4];
    __nv_bfloat16* Ah = (__nv_bfloat16*)sm;                    // [176][40]
    __nv_bfloat16* Al = (__nv_bfloat16*)(sm + 14080);          // [176][40]
    __nv_bfloat16* Bh = (__nv_bfloat16*)(sm + 28160);          // [64][40]
    __nv_bfloat16* Bl = (__nv_bfloat16*)(sm + 33280);          // [64][40]
    float* hb = (float*)sm;                                    // [176][68]

    const int t  = threadIdx.x;
    const int w  = t >> 5;
    const int l  = t & 31;
    const int g  = l >> 2;
    const int t4 = l & 3;
    const int n0 = blockIdx.x * 64;
    const int m0 = blockIdx.y * 176;

    float acc[11][4];
#pragma unroll
    for (int mt = 0; mt < 11; mt++)
#pragma unroll
        for (int j = 0; j < 4; j++) acc[mt][j] = 0.0f;

    for (int kc = 0; kc < 4; kc++) {
        const int k0 = kc * 32;
        // ---- stage A [176 x 32] as bf16 hi/lo, stride 40 ----
#pragma unroll
        for (int j = 0; j < 6; j++) {
            int flat = j * 256 + t;           // float4 index over [176][8]
            if (flat < 1408) {
                int m  = flat >> 3;
                int kq = (flat & 7) * 4;
                float4 v = *(const float4*)&x[(size_t)(m0 + m) * INDIM + k0 + kq];
                uint32_t h0, l0, h1, l1;
                bf16_split2(v.x, v.y, h0, l0);
                bf16_split2(v.z, v.w, h1, l1);
                *(uint32_t*)&Ah[m * 40 + kq]     = h0;
                *(uint32_t*)&Ah[m * 40 + kq + 2] = h1;
                *(uint32_t*)&Al[m * 40 + kq]     = l0;
                *(uint32_t*)&Al[m * 40 + kq + 2] = l1;
            }
        }
        // ---- stage B^T [64 n x 32 k] with inline We1 fold ----
#pragma unroll
        for (int j = 0; j < 8; j++) {
            int flat = j * 256 + t;
            int kl = flat >> 6;               // 0..31
            int n  = flat & 63;
            float v = We1[(size_t)(k0 + kl) * HID + n0 + n]
                    + We1[(size_t)(k0 + kl + INDIM) * HID + n0 + n];
            __nv_bfloat16 h = __float2bfloat16_rn(v);
            float r = v - __bfloat162float(h);
            Bh[n * 40 + kl] = h;
            Bl[n * 40 + kl] = __float2bfloat16_rn(r);
        }
        __syncthreads();

        // ---- compute: 2 k16-steps ----
#pragma unroll
        for (int ks = 0; ks < 2; ks++) {
            const int kb = ks * 16 + 2 * t4;
            const __nv_bfloat16* brow = Bh + (8 * w + g) * 40 + kb;
            const __nv_bfloat16* brol = Bl + (8 * w + g) * 40 + kb;
            uint32_t bh0 = lds_u32(brow);
            uint32_t bh1 = lds_u32(brow + 8);
            uint32_t bl0 = lds_u32(brol);
            uint32_t bl1 = lds_u32(brol + 8);
#pragma unroll
            for (int mt = 0; mt < 11; mt++) {
                const int rb = mt * 16;
                uint32_t ah[4], al[4];
                ah[0] = lds_u32(Ah + (rb + g) * 40 + kb);
                ah[1] = lds_u32(Ah + (rb + g + 8) * 40 + kb);
                ah[2] = lds_u32(Ah + (rb + g) * 40 + kb + 8);
                ah[3] = lds_u32(Ah + (rb + g + 8) * 40 + kb + 8);
                al[0] = lds_u32(Al + (rb + g) * 40 + kb);
                al[1] = lds_u32(Al + (rb + g + 8) * 40 + kb);
                al[2] = lds_u32(Al + (rb + g) * 40 + kb + 8);
                al[3] = lds_u32(Al + (rb + g + 8) * 40 + kb + 8);
                mma_bf16(acc[mt], ah, bh0, bh1);
                mma_bf16(acc[mt], ah, bl0, bl1);
                mma_bf16(acc[mt], al, bh0, bh1);
            }
        }
        __syncthreads();
    }

    // ---- epilogue: relu(acc + bias) -> hbuf f32 [176][68] ----
    const int   cc  = 8 * w + 2 * t4;
    const float bv0 = be1[n0 + cc];
    const float bv1 = be1[n0 + cc + 1];
#pragma unroll
    for (int mt = 0; mt < 11; mt++) {
        const int r0 = mt * 16 + g;
        const int r1 = r0 + 8;
        hb[r0 * 68 + cc]     = fmaxf(acc[mt][0] + bv0, 0.0f);
        hb[r0 * 68 + cc + 1] = fmaxf(acc[mt][1] + bv1, 0.0f);
        hb[r1 * 68 + cc]     = fmaxf(acc[mt][2] + bv0, 0.0f);
        hb[r1 * 68 + cc + 1] = fmaxf(acc[mt][3] + bv1, 0.0f);
    }
    __syncthreads();

    // ---- 22-row segment reduce: 8 groups x 64 cols, 2 outputs/thread ----
    {
        const int c = t & 63;
#pragma unroll
        for (int hh = 0; hh < 2; hh++) {
            const int gg = (t >> 6) + hh * 4;   // 0..7
            float s = 0.0f;
#pragma unroll
            for (int i = 0; i < 22; i++)
                s += hb[(gg * 22 + i) * 68 + c];
            g_hs[(size_t)(blockIdx.y * 8 + gg) * HID + n0 + c] = s;
        }
    }
}

// ---------------------------------------------------------------------------
// Tail: C[512,256] = act(A @ W + biasScale*bias) on bf16-split2 mma.
// Block = 16x32 tile, 128 threads, warp split-K (64 each) + smem reduce.
// Weights read from g_Wt (pre-transposed in K1) -> pure float4 staging.
// smem = exactly 48KB: Ah/Al[16][256]bf16 + Bh/Bl[32][256]bf16 (XOR swizzle).
// ---------------------------------------------------------------------------
template <bool RELU, bool BCAST>
__global__ __launch_bounds__(128)
void tail_bf16(const float* __restrict__ A,
               int mat,
               const float* __restrict__ bias,
               float biasScale,
               float* __restrict__ C) {
    __shared__ __align__(16) unsigned char sm[49152];
    __nv_bfloat16* Ah = (__nv_bfloat16*)sm;             // [16][256]
    __nv_bfloat16* Al = (__nv_bfloat16*)(sm + 8192);
    __nv_bfloat16* Bh = (__nv_bfloat16*)(sm + 16384);   // [32][256]
    __nv_bfloat16* Bl = (__nv_bfloat16*)(sm + 32768);
    typedef float RedT[16][33];
    RedT* red = (RedT*)(sm + 16384);                    // alias Bh (post-sync)

    const int t  = threadIdx.x;
    const int w  = t >> 5;
    const int l  = t & 31;
    const int g  = l >> 2;
    const int t4 = l & 3;
    const int m0 = blockIdx.y * 16;
    const int n0 = blockIdx.x * 32;

    const float* Wt = g_Wt + (size_t)mat * HID * HID;

    // ---- stage A [16 x 256]: float4 + split, XOR swizzle k^(8*(m&7)) ----
#pragma unroll
    for (int j = 0; j < 8; j++) {
        int flat = j * 128 + t;
        int m  = flat >> 6;
        int kq = (flat & 63) * 4;
        float4 v = *(const float4*)&A[(size_t)(m0 + m) * HID + kq];
        uint32_t h0, l0, h1, l1;
        bf16_split2(v.x, v.y, h0, l0);
        bf16_split2(v.z, v.w, h1, l1);
        int kx = kq ^ (8 * (m & 7));
        *(uint32_t*)&Ah[m * 256 + kx]     = h0;
        *(uint32_t*)&Ah[m * 256 + kx + 2] = h1;
        *(uint32_t*)&Al[m * 256 + kx]     = l0;
        *(uint32_t*)&Al[m * 256 + kx + 2] = l1;
    }
    // ---- stage B^T [32 n x 256 k] from Wt (k-contig) ----
#pragma unroll
    for (int j = 0; j < 16; j++) {
        int flat = j * 128 + t;
        int n  = flat >> 6;
        int kq = (flat & 63) * 4;
        float4 v = *(const float4*)&Wt[(size_t)(n0 + n) * HID + kq];
        uint32_t h0, l0, h1, l1;
        bf16_split2(v.x, v.y, h0, l0);
        bf16_split2(v.z, v.w, h1, l1);
        int kx = kq ^ (8 * (n & 7));
        *(uint32_t*)&Bh[n * 256 + kx]     = h0;
        *(uint32_t*)&Bh[n * 256 + kx + 2] = h1;
        *(uint32_t*)&Bl[n * 256 + kx]     = l0;
        *(uint32_t*)&Bl[n * 256 + kx + 2] = l1;
    }
    __syncthreads();

    // ---- compute: warp w covers k in [64w, 64w+64), 4 k16-steps ----
    float acc[4][4];
#pragma unroll
    for (int nt = 0; nt < 4; nt++)
#pragma unroll
        for (int j = 0; j < 4; j++) acc[nt][j] = 0.0f;

#pragma unroll
    for (int ks = 0; ks < 4; ks++) {
        const int kb  = 64 * w + 16 * ks;
        const int ka0 = (kb + 2 * t4) ^ (8 * g);      // rows g / g+8 share (m&7)=g
        const int ka2 = (kb + 2 * t4 + 8) ^ (8 * g);

        uint32_t ah[4], al[4];
        ah[0] = lds_u32(Ah + g * 256 + ka0);
        ah[1] = lds_u32(Ah + (g + 8) * 256 + ka0);
        ah[2] = lds_u32(Ah + g * 256 + ka2);
        ah[3] = lds_u32(Ah + (g + 8) * 256 + ka2);
        al[0] = lds_u32(Al + g * 256 + ka0);
        al[1] = lds_u32(Al + (g + 8) * 256 + ka0);
        al[2] = lds_u32(Al + g * 256 + ka2);
        al[3] = lds_u32(Al + (g + 8) * 256 + ka2);

#pragma unroll
        for (int nt = 0; nt < 4; nt++) {
            const int n = nt * 8 + g;                 // n&7 == g -> same swizzle
            uint32_t bh0 = lds_u32(Bh + n * 256 + ka0);
            uint32_t bh1 = lds_u32(Bh + n * 256 + ka2);
            uint32_t bl0 = lds_u32(Bl + n * 256 + ka0);
            uint32_t bl1 = lds_u32(Bl + n * 256 + ka2);
            mma_bf16(acc[nt], ah, bh0, bh1);
            mma_bf16(acc[nt], ah, bl0, bl1);
            mma_bf16(acc[nt], al, bh0, bh1);
        }
    }
    __syncthreads();   // done reading Bh/Bl -> reuse as reduce scratch

    // ---- cross-warp split-K reduce ----
#pragma unroll
    for (int nt = 0; nt < 4; nt++) {
        const int col = nt * 8 + 2 * t4;
        red[w][g][col]         = acc[nt][0];
        red[w][g][col + 1]     = acc[nt][1];
        red[w][g + 8][col]     = acc[nt][2];
        red[w][g + 8][col + 1] = acc[nt][3];
    }
    __syncthreads();

    // ---- epilogue: thread owns 4 consecutive cols of one row ----
    const int row = t >> 3;
    const int cb  = (t & 7) * 4;
    float v[4];
#pragma unroll
    for (int j = 0; j < 4; j++)
        v[j] = red[0][row][cb + j] + red[1][row][cb + j]
             + red[2][row][cb + j] + red[3][row][cb + j];

    const float4 bv = *(const float4*)&bias[n0 + cb];
    float4 o;
    o.x = v[0] + biasScale * bv.x;
    o.y = v[1] + biasScale * bv.y;
    o.z = v[2] + biasScale * bv.z;
    o.w = v[3] + biasScale * bv.w;
    if (RELU) {
        o.x = fmaxf(o.x, 0.0f); o.y = fmaxf(o.y, 0.0f);
        o.z = fmaxf(o.z, 0.0f); o.w = fmaxf(o.w, 0.0f);
    }

    const int rowg = m0 + row;
    const int colg = n0 + cb;
    if (!BCAST) {
        *(float4*)&C[(size_t)rowg * HID + colg] = o;
    } else {
        size_t base = ((size_t)rowg * NNODE) * HID + colg;
#pragma unroll
        for (int p = 0; p < NNODE; p++)
            *(float4*)&C[base + (size_t)p * HID] = o;
    }
}

// ---------------------------------------------------------------------------
extern "C" void kernel_launch(void* const* d_in, const int* in_sizes, int n_in,
                              void* d_out, int out_size) {
    const float* x   = (const float*)d_in[0];
    const float* We1 = (const float*)d_in[1];
    const float* be1 = (const float*)d_in[2];
    const float* We2 = (const float*)d_in[3];
    const float* be2 = (const float*)d_in[4];
    const float* Wn1 = (const float*)d_in[5];
    const float* bn1 = (const float*)d_in[6];
    const float* Wn2 = (const float*)d_in[7];
    const float* bn2 = (const float*)d_in[8];
    float* out = (float*)d_out;

    float *phs, *pS, *pt;
    cudaGetSymbolAddress((void**)&phs, g_hs);
    cudaGetSymbolAddress((void**)&pS,  g_S);
    cudaGetSymbolAddress((void**)&pt,  g_t);

    // K1 (+ fused tail-weight transpose): -> g_hs [512 x 256], g_Wt
    k1_mma<<<dim3(4, 67), 256>>>(x, We1, be1, We2, Wn1, Wn2);

    dim3 tg(HID / 32, BSZ / 16);   // (8, 32) = 256 blocks

    // L0: S = hs @ We2 + 22*be2
    tail_bf16<false, false><<<tg, 128>>>(phs, 0, be2, (float)NNODE, pS);
    // L1: t = relu(S @ Wn1 + bn1)
    tail_bf16<true,  false><<<tg, 128>>>(pS,  1, bn1, 1.0f, pt);
    // L2: out = t @ Wn2 + bn2, broadcast over 22 nodes
    tail_bf16<false, true ><<<tg, 128>>>(pt,  2, bn2, 1.0f, out);
}